// round 2
// baseline (speedup 1.0000x reference)
#include <cuda_runtime.h>
#include <cuda_fp16.h>
#include <math.h>
#include <stdint.h>

#define B_    2
#define S_    2048
#define H_    1024
#define E_    8
#define FF_   4096
#define T_    (B_ * S_)        // 4096 tokens
#define SLOTS (T_ * 2)         // 8192 (every token gets exactly 2 slots)
#define SLOTS_PAD (SLOTS + 128)

// ---------------- scratch (static __device__ — no allocations) ----------------
__device__ int    g_counts[E_];
__device__ int    g_offsets[E_ + 1];
__device__ int    g_cursor[E_];
__device__ int    g_tok_e[T_][2];
__device__ float  g_tok_g[T_][2];
__device__ int    g_tok_slot[T_][2];
__device__ float  g_mu[T_];
__device__ float  g_rstd[T_];
__device__ int    g_slot_token[SLOTS_PAD];
__device__ int    g_slot_expert[SLOTS_PAD];
__device__ __half g_Hbuf[(size_t)SLOTS_PAD * H_];          // 17 MB  (post-LN rows, fp16)
__device__ __half g_Abuf[(size_t)SLOTS_PAD * FF_];         // 68 MB  (GELU activations, fp16)
__device__ float  g_Ybuf[(size_t)SLOTS_PAD * H_];          // 34 MB  (per-slot FFN outputs)
__device__ __half g_W1h[(size_t)E_ * H_ * FF_];            // 67 MB
__device__ __half g_W2h[(size_t)E_ * FF_ * H_];            // 67 MB

// ---------------- small kernels ----------------
__global__ void zero_kernel() {
    if (threadIdx.x < E_) g_counts[threadIdx.x] = 0;
}

__global__ void convert_kernel(const float* __restrict__ W1, const float* __restrict__ W2) {
    const size_t n4 = (size_t)E_ * H_ * FF_ / 4;
    size_t stride = (size_t)gridDim.x * blockDim.x;
    for (size_t i = (size_t)blockIdx.x * blockDim.x + threadIdx.x; i < n4; i += stride) {
        float4 a = ((const float4*)W1)[i];
        ((__half2*)g_W1h)[2 * i]     = __floats2half2_rn(a.x, a.y);
        ((__half2*)g_W1h)[2 * i + 1] = __floats2half2_rn(a.z, a.w);
        float4 b = ((const float4*)W2)[i];
        ((__half2*)g_W2h)[2 * i]     = __floats2half2_rn(b.x, b.y);
        ((__half2*)g_W2h)[2 * i + 1] = __floats2half2_rn(b.z, b.w);
    }
}

// one block (256 threads) per token: LN stats + router logits + top-2 softmax
__global__ void router_kernel(const float* __restrict__ x,
                              const float* __restrict__ rW,
                              const float* __restrict__ rb) {
    int t = blockIdx.x;
    int tid = threadIdx.x;
    float4 xv = ((const float4*)(x + (size_t)t * H_))[tid];
    float vals[4] = {xv.x, xv.y, xv.z, xv.w};
    float red[10];
#pragma unroll
    for (int i = 0; i < 10; i++) red[i] = 0.f;
#pragma unroll
    for (int j = 0; j < 4; j++) {
        float v = vals[j];
        red[0] += v;
        red[1] += v * v;
        const float4* w4 = (const float4*)(rW + (size_t)(tid * 4 + j) * E_);
        float4 wa = w4[0], wb = w4[1];
        red[2] += v * wa.x; red[3] += v * wa.y; red[4] += v * wa.z; red[5] += v * wa.w;
        red[6] += v * wb.x; red[7] += v * wb.y; red[8] += v * wb.z; red[9] += v * wb.w;
    }
#pragma unroll
    for (int o = 16; o > 0; o >>= 1)
#pragma unroll
        for (int i = 0; i < 10; i++)
            red[i] += __shfl_down_sync(0xffffffffu, red[i], o);
    __shared__ float sred[8][10];
    if ((tid & 31) == 0)
#pragma unroll
        for (int i = 0; i < 10; i++) sred[tid >> 5][i] = red[i];
    __syncthreads();
    if (tid == 0) {
        float f[10];
#pragma unroll
        for (int i = 0; i < 10; i++) {
            float s = 0.f;
#pragma unroll
            for (int w = 0; w < 8; w++) s += sred[w][i];
            f[i] = s;
        }
        float mu  = f[0] * (1.0f / H_);
        float var = f[1] * (1.0f / H_) - mu * mu;
        g_mu[t]   = mu;
        g_rstd[t] = rsqrtf(var + 1e-5f);
        float l[E_];
#pragma unroll
        for (int e = 0; e < E_; e++) l[e] = f[2 + e] + rb[e];
        int i0 = 0;
#pragma unroll
        for (int e = 1; e < E_; e++) if (l[e] > l[i0]) i0 = e;
        int i1 = -1;
#pragma unroll
        for (int e = 0; e < E_; e++)
            if (e != i0 && (i1 < 0 || l[e] > l[i1])) i1 = e;
        float ex = expf(l[i1] - l[i0]);
        float g0 = 1.f / (1.f + ex);
        float g1 = ex / (1.f + ex);
        g_tok_e[t][0] = i0; g_tok_e[t][1] = i1;
        g_tok_g[t][0] = g0; g_tok_g[t][1] = g1;
        atomicAdd(&g_counts[i0], 1);
        atomicAdd(&g_counts[i1], 1);
    }
}

__global__ void offsets_kernel() {
    if (threadIdx.x == 0) {
        int off = 0;
#pragma unroll
        for (int e = 0; e < E_; e++) {
            g_offsets[e] = off;
            g_cursor[e]  = off;
            off += g_counts[e];
        }
        g_offsets[E_] = off;
    }
}

__global__ void scatter_kernel() {
    int t = blockIdx.x * blockDim.x + threadIdx.x;
    if (t < T_) {
#pragma unroll
        for (int s = 0; s < 2; s++) {
            int e = g_tok_e[t][s];
            int pos = atomicAdd(&g_cursor[e], 1);
            g_slot_token[pos]  = t;
            g_slot_expert[pos] = e;
            g_tok_slot[t][s]   = pos;
        }
    }
}

// one block per slot row: apply LN affine for the owning expert, write fp16
__global__ void gather_kernel(const float* __restrict__ x,
                              const float* __restrict__ ln_g,
                              const float* __restrict__ ln_b) {
    int r = blockIdx.x;
    int t = g_slot_token[r];
    int e = g_slot_expert[r];
    float mu = g_mu[t], rs = g_rstd[t];
    int c = threadIdx.x * 4;
    float4 xv = *(const float4*)(x    + (size_t)t * H_ + c);
    float4 gv = *(const float4*)(ln_g + (size_t)e * H_ + c);
    float4 bv = *(const float4*)(ln_b + (size_t)e * H_ + c);
    float h0 = (xv.x - mu) * rs * gv.x + bv.x;
    float h1 = (xv.y - mu) * rs * gv.y + bv.y;
    float h2 = (xv.z - mu) * rs * gv.z + bv.z;
    float h3 = (xv.w - mu) * rs * gv.w + bv.w;
    __half2* dst = (__half2*)(g_Hbuf + (size_t)r * H_ + c);
    dst[0] = __floats2half2_rn(h0, h1);
    dst[1] = __floats2half2_rn(h2, h3);
}

// final combine: out[t] = x[t] + g0 * Y[slot0] + g1 * Y[slot1]   (deterministic)
__global__ void combine_kernel(const float* __restrict__ x, float* __restrict__ out) {
    int t = blockIdx.x;
    int c = threadIdx.x * 4;
    int s0 = g_tok_slot[t][0], s1 = g_tok_slot[t][1];
    float g0 = g_tok_g[t][0],  g1 = g_tok_g[t][1];
    float4 xv = *(const float4*)(x + (size_t)t * H_ + c);
    float4 y0 = *(const float4*)(g_Ybuf + (size_t)s0 * H_ + c);
    float4 y1 = *(const float4*)(g_Ybuf + (size_t)s1 * H_ + c);
    float4 o;
    o.x = xv.x + g0 * y0.x + g1 * y1.x;
    o.y = xv.y + g0 * y0.y + g1 * y1.y;
    o.z = xv.z + g0 * y0.z + g1 * y1.z;
    o.w = xv.w + g0 * y0.w + g1 * y1.w;
    *(float4*)(out + (size_t)t * H_ + c) = o;
}

// ---------------- grouped GEMM (mma.sync fp16, cp.async double-buffered) ----------------
#define BM 128
#define BN 64
#define BK 32
#define ASTR (BK + 8)   // 40 halfs
#define BSTR (BN + 8)   // 72 halfs

__device__ __forceinline__ float gelu_exact(float v) {
    return 0.5f * v * (1.0f + erff(v * 0.70710678118654752f));
}

__device__ __forceinline__ void cp_async16(uint32_t dst, const void* src) {
    asm volatile("cp.async.cg.shared.global [%0], [%1], 16;" :: "r"(dst), "l"(src));
}

template <int KDIM, int NDIM>
__global__ void __launch_bounds__(256, 2)
gemm_kernel(const float* __restrict__ bias) {
    constexpr bool FFN1 = (NDIM == FF_);
    const int e   = blockIdx.z;
    const int m0  = g_offsets[e];
    const int cnt = g_offsets[e + 1] - m0;
    const int mt  = blockIdx.y;
    if (mt * BM >= cnt) return;
    const int n0  = blockIdx.x * BN;

    const __half* Ag = (FFN1 ? g_Hbuf : g_Abuf) + (size_t)(m0 + mt * BM) * KDIM;
    const __half* Bg = (FFN1 ? g_W1h : g_W2h) + (size_t)e * KDIM * NDIM + n0;

    __shared__ __half As[2][BM][ASTR];
    __shared__ __half Bs[2][BK][BSTR];

    const int tid = threadIdx.x;
    const int wid = tid >> 5, lane = tid & 31;
    const int wm = (wid & 3) * 32, wn = (wid >> 2) * 32;

    // global->smem mapping: A = 512 vec8 (2/thread), B = 256 vec8 (1/thread)
    const int ar0 = tid >> 2,        ac0 = (tid & 3) * 8;
    const int ar1 = (tid + 256) >> 2, ac1 = ((tid + 256) & 3) * 8;
    const int br  = tid >> 3,        bc  = (tid & 7) * 8;

    auto stage_load = [&](int buf, int k0) {
        cp_async16((uint32_t)__cvta_generic_to_shared(&As[buf][ar0][ac0]),
                   Ag + (size_t)ar0 * KDIM + k0 + ac0);
        cp_async16((uint32_t)__cvta_generic_to_shared(&As[buf][ar1][ac1]),
                   Ag + (size_t)ar1 * KDIM + k0 + ac1);
        cp_async16((uint32_t)__cvta_generic_to_shared(&Bs[buf][br][bc]),
                   Bg + (size_t)(k0 + br) * NDIM + bc);
        asm volatile("cp.async.commit_group;" ::: "memory");
    };

    float acc[2][4][4];
#pragma unroll
    for (int i = 0; i < 2; i++)
#pragma unroll
        for (int j = 0; j < 4; j++)
#pragma unroll
            for (int k = 0; k < 4; k++) acc[i][j][k] = 0.f;

    constexpr int KT = KDIM / BK;
    stage_load(0, 0);

    for (int kt = 0; kt < KT; kt++) {
        if (kt + 1 < KT) {
            stage_load((kt + 1) & 1, (kt + 1) * BK);
            asm volatile("cp.async.wait_group 1;" ::: "memory");
        } else {
            asm volatile("cp.async.wait_group 0;" ::: "memory");
        }
        __syncthreads();
        const int buf = kt & 1;
#pragma unroll
        for (int kk = 0; kk < BK; kk += 16) {
            uint32_t a[2][4];
#pragma unroll
            for (int mi = 0; mi < 2; mi++) {
                uint32_t addr = (uint32_t)__cvta_generic_to_shared(
                    &As[buf][wm + mi * 16 + (lane & 15)][kk + (lane >> 4) * 8]);
                asm volatile("ldmatrix.sync.aligned.m8n8.x4.shared.b16 {%0,%1,%2,%3}, [%4];"
                             : "=r"(a[mi][0]), "=r"(a[mi][1]), "=r"(a[mi][2]), "=r"(a[mi][3])
                             : "r"(addr));
            }
            uint32_t b[4][2];
#pragma unroll
            for (int nj = 0; nj < 4; nj += 2) {
                uint32_t addr = (uint32_t)__cvta_generic_to_shared(
                    &Bs[buf][kk + (lane & 15)][wn + nj * 8 + (lane >> 4) * 8]);
                uint32_t r0, r1, r2, r3;
                asm volatile("ldmatrix.sync.aligned.m8n8.x4.trans.shared.b16 {%0,%1,%2,%3}, [%4];"
                             : "=r"(r0), "=r"(r1), "=r"(r2), "=r"(r3)
                             : "r"(addr));
                b[nj][0] = r0; b[nj][1] = r1;
                b[nj + 1][0] = r2; b[nj + 1][1] = r3;
            }
#pragma unroll
            for (int mi = 0; mi < 2; mi++)
#pragma unroll
                for (int nj = 0; nj < 4; nj++)
                    asm volatile(
                        "mma.sync.aligned.m16n8k16.row.col.f32.f16.f16.f32 "
                        "{%0,%1,%2,%3},{%4,%5,%6,%7},{%8,%9},{%0,%1,%2,%3};"
                        : "+f"(acc[mi][nj][0]), "+f"(acc[mi][nj][1]),
                          "+f"(acc[mi][nj][2]), "+f"(acc[mi][nj][3])
                        : "r"(a[mi][0]), "r"(a[mi][1]), "r"(a[mi][2]), "r"(a[mi][3]),
                          "r"(b[nj][0]), "r"(b[nj][1]));
        }
        __syncthreads();
    }

    // epilogue
#pragma unroll
    for (int mi = 0; mi < 2; mi++) {
#pragma unroll
        for (int nj = 0; nj < 4; nj++) {
            const int r0  = wm + mi * 16 + (lane >> 2);
            const int col = wn + nj * 8 + (lane & 3) * 2;
#pragma unroll
            for (int h = 0; h < 2; h++) {
                const int r = r0 + h * 8;
                if (mt * BM + r < cnt) {
                    const float b0 = bias[(size_t)e * NDIM + n0 + col];
                    const float b1 = bias[(size_t)e * NDIM + n0 + col + 1];
                    float v0 = acc[mi][nj][2 * h]     + b0;
                    float v1 = acc[mi][nj][2 * h + 1] + b1;
                    const int slot = m0 + mt * BM + r;
                    if (FFN1) {
                        v0 = gelu_exact(v0);
                        v1 = gelu_exact(v1);
                        *(__half2*)(g_Abuf + (size_t)slot * FF_ + n0 + col) =
                            __floats2half2_rn(v0, v1);
                    } else {
                        float2* dst = (float2*)(g_Ybuf + (size_t)slot * H_ + n0 + col);
                        *dst = make_float2(v0, v1);
                    }
                }
            }
        }
    }
}

// ---------------- launch ----------------
extern "C" void kernel_launch(void* const* d_in, const int* in_sizes, int n_in,
                              void* d_out, int out_size) {
    (void)in_sizes; (void)n_in; (void)out_size;
    const float* x    = (const float*)d_in[0];
    const float* rW   = (const float*)d_in[1];
    const float* rb   = (const float*)d_in[2];
    const float* ln_g = (const float*)d_in[3];
    const float* ln_b = (const float*)d_in[4];
    const float* W1   = (const float*)d_in[5];
    const float* b1   = (const float*)d_in[6];
    const float* W2   = (const float*)d_in[7];
    const float* b2   = (const float*)d_in[8];
    float* out = (float*)d_out;

    zero_kernel<<<1, 32>>>();
    convert_kernel<<<2048, 256>>>(W1, W2);
    router_kernel<<<T_, 256>>>(x, rW, rb);
    offsets_kernel<<<1, 32>>>();
    scatter_kernel<<<T_ / 256, 256>>>();
    gather_kernel<<<SLOTS, 256>>>(x, ln_g, ln_b);
    gemm_kernel<H_, FF_><<<dim3(FF_ / BN, 32, E_), 256>>>(b1);
    gemm_kernel<FF_, H_><<<dim3(H_ / BN, 32, E_), 256>>>(b2);
    combine_kernel<<<T_, 256>>>(x, out);
}

// round 8
// speedup vs baseline: 1.1586x; 1.1586x over previous
#include <cuda_runtime.h>
#include <cuda_fp16.h>
#include <math.h>
#include <stdint.h>

#define B_    2
#define S_    2048
#define H_    1024
#define E_    8
#define FF_   4096
#define T_    (B_ * S_)
#define SLOTS (T_ * 2)
#define SLOTS_PAD (SLOTS + 128)

// ---------------- scratch (static __device__ — no allocations) ----------------
__device__ int    g_counts[E_];
__device__ int    g_offsets[E_ + 1];
__device__ int    g_cursor[E_];
__device__ int    g_tok_e[T_][2];
__device__ float  g_tok_g[T_][2];
__device__ int    g_tok_slot[T_][2];
__device__ float  g_mu[T_];
__device__ float  g_rstd[T_];
__device__ int    g_slot_token[SLOTS_PAD];
__device__ int    g_slot_expert[SLOTS_PAD];
__device__ __half g_Hbuf[(size_t)SLOTS_PAD * H_];          // post-LN rows, fp16
__device__ __half g_Abuf[(size_t)SLOTS_PAD * FF_];         // GELU activations, fp16
__device__ float  g_Ybuf[(size_t)SLOTS_PAD * H_];          // per-slot FFN outputs fp32
__device__ __half g_W1h[(size_t)E_ * H_ * FF_];            // [e][h][f]
__device__ __half g_W2h[(size_t)E_ * FF_ * H_];            // [e][f][h]

// ---------------- small kernels ----------------
__global__ void zero_kernel() {
    if (threadIdx.x < E_) g_counts[threadIdx.x] = 0;
}

__global__ void convert_kernel(const float* __restrict__ W1, const float* __restrict__ W2) {
    const size_t n4 = (size_t)E_ * H_ * FF_ / 4;
    size_t stride = (size_t)gridDim.x * blockDim.x;
    for (size_t i = (size_t)blockIdx.x * blockDim.x + threadIdx.x; i < n4; i += stride) {
        float4 a = ((const float4*)W1)[i];
        ((__half2*)g_W1h)[2 * i]     = __floats2half2_rn(a.x, a.y);
        ((__half2*)g_W1h)[2 * i + 1] = __floats2half2_rn(a.z, a.w);
        float4 b = ((const float4*)W2)[i];
        ((__half2*)g_W2h)[2 * i]     = __floats2half2_rn(b.x, b.y);
        ((__half2*)g_W2h)[2 * i + 1] = __floats2half2_rn(b.z, b.w);
    }
}

// one block (256 threads) per token: LN stats + router logits + top-2 softmax
__global__ void router_kernel(const float* __restrict__ x,
                              const float* __restrict__ rW,
                              const float* __restrict__ rb) {
    int t = blockIdx.x;
    int tid = threadIdx.x;
    float4 xv = ((const float4*)(x + (size_t)t * H_))[tid];
    float vals[4] = {xv.x, xv.y, xv.z, xv.w};
    float red[10];
#pragma unroll
    for (int i = 0; i < 10; i++) red[i] = 0.f;
#pragma unroll
    for (int j = 0; j < 4; j++) {
        float v = vals[j];
        red[0] += v;
        red[1] += v * v;
        const float4* w4 = (const float4*)(rW + (size_t)(tid * 4 + j) * E_);
        float4 wa = w4[0], wb = w4[1];
        red[2] += v * wa.x; red[3] += v * wa.y; red[4] += v * wa.z; red[5] += v * wa.w;
        red[6] += v * wb.x; red[7] += v * wb.y; red[8] += v * wb.z; red[9] += v * wb.w;
    }
#pragma unroll
    for (int o = 16; o > 0; o >>= 1)
#pragma unroll
        for (int i = 0; i < 10; i++)
            red[i] += __shfl_down_sync(0xffffffffu, red[i], o);
    __shared__ float sred[8][10];
    if ((tid & 31) == 0)
#pragma unroll
        for (int i = 0; i < 10; i++) sred[tid >> 5][i] = red[i];
    __syncthreads();
    if (tid == 0) {
        float f[10];
#pragma unroll
        for (int i = 0; i < 10; i++) {
            float s = 0.f;
#pragma unroll
            for (int w = 0; w < 8; w++) s += sred[w][i];
            f[i] = s;
        }
        float mu  = f[0] * (1.0f / H_);
        float var = f[1] * (1.0f / H_) - mu * mu;
        g_mu[t]   = mu;
        g_rstd[t] = rsqrtf(var + 1e-5f);
        float l[E_];
#pragma unroll
        for (int e = 0; e < E_; e++) l[e] = f[2 + e] + rb[e];
        int i0 = 0;
#pragma unroll
        for (int e = 1; e < E_; e++) if (l[e] > l[i0]) i0 = e;
        int i1 = -1;
#pragma unroll
        for (int e = 0; e < E_; e++)
            if (e != i0 && (i1 < 0 || l[e] > l[i1])) i1 = e;
        float ex = expf(l[i1] - l[i0]);
        float g0 = 1.f / (1.f + ex);
        float g1 = ex / (1.f + ex);
        g_tok_e[t][0] = i0; g_tok_e[t][1] = i1;
        g_tok_g[t][0] = g0; g_tok_g[t][1] = g1;
        atomicAdd(&g_counts[i0], 1);
        atomicAdd(&g_counts[i1], 1);
    }
}

__global__ void offsets_kernel() {
    if (threadIdx.x == 0) {
        int off = 0;
#pragma unroll
        for (int e = 0; e < E_; e++) {
            g_offsets[e] = off;
            g_cursor[e]  = off;
            off += g_counts[e];
        }
        g_offsets[E_] = off;
    }
}

__global__ void scatter_kernel() {
    int t = blockIdx.x * blockDim.x + threadIdx.x;
    if (t < T_) {
#pragma unroll
        for (int s = 0; s < 2; s++) {
            int e = g_tok_e[t][s];
            int pos = atomicAdd(&g_cursor[e], 1);
            g_slot_token[pos]  = t;
            g_slot_expert[pos] = e;
            g_tok_slot[t][s]   = pos;
        }
    }
}

__global__ void gather_kernel(const float* __restrict__ x,
                              const float* __restrict__ ln_g,
                              const float* __restrict__ ln_b) {
    int r = blockIdx.x;
    int t = g_slot_token[r];
    int e = g_slot_expert[r];
    float mu = g_mu[t], rs = g_rstd[t];
    int c = threadIdx.x * 4;
    float4 xv = *(const float4*)(x    + (size_t)t * H_ + c);
    float4 gv = *(const float4*)(ln_g + (size_t)e * H_ + c);
    float4 bv = *(const float4*)(ln_b + (size_t)e * H_ + c);
    float h0 = (xv.x - mu) * rs * gv.x + bv.x;
    float h1 = (xv.y - mu) * rs * gv.y + bv.y;
    float h2 = (xv.z - mu) * rs * gv.z + bv.z;
    float h3 = (xv.w - mu) * rs * gv.w + bv.w;
    __half2* dst = (__half2*)(g_Hbuf + (size_t)r * H_ + c);
    dst[0] = __floats2half2_rn(h0, h1);
    dst[1] = __floats2half2_rn(h2, h3);
}

__global__ void combine_kernel(const float* __restrict__ x, float* __restrict__ out) {
    int t = blockIdx.x;
    int c = threadIdx.x * 4;
    int s0 = g_tok_slot[t][0], s1 = g_tok_slot[t][1];
    float g0 = g_tok_g[t][0],  g1 = g_tok_g[t][1];
    float4 xv = *(const float4*)(x + (size_t)t * H_ + c);
    float4 y0 = *(const float4*)(g_Ybuf + (size_t)s0 * H_ + c);
    float4 y1 = *(const float4*)(g_Ybuf + (size_t)s1 * H_ + c);
    float4 o;
    o.x = xv.x + g0 * y0.x + g1 * y1.x;
    o.y = xv.y + g0 * y0.y + g1 * y1.y;
    o.z = xv.z + g0 * y0.z + g1 * y1.z;
    o.w = xv.w + g0 * y0.w + g1 * y1.w;
    *(float4*)(out + (size_t)t * H_ + c) = o;
}

// ---------------- grouped GEMM (mma.sync fp16, static smem, double-buffered) ----
// CTA tile 128x128, BK=32. 8 warps (2 M x 4 N), warp tile 64x32.
// Static shared: 2*(128*40 + 32*136)*2B = 37,888 B  (< 48 KB, no attribute call)
#define BM 128
#define BN 128
#define BK 32
#define ASTR (BK + 8)    // 40 halfs
#define BSTR (BN + 8)    // 136 halfs

__device__ __forceinline__ float gelu_exact(float v) {
    return 0.5f * v * (1.0f + erff(v * 0.70710678118654752f));
}
__device__ __forceinline__ void cp_async16(uint32_t dst, const void* src) {
    asm volatile("cp.async.cg.shared.global [%0], [%1], 16;" :: "r"(dst), "l"(src));
}
__device__ __forceinline__ uint32_t smem_u32(const void* p) {
    uint32_t a;
    asm("{ .reg .u64 t; cvta.to.shared.u64 t, %1; cvt.u32.u64 %0, t; }" : "=r"(a) : "l"(p));
    return a;
}

template <int KDIM, int NDIM, bool FFN1>
__global__ void __launch_bounds__(256, 2)
gemm_kernel(const float* __restrict__ bias) {
    __shared__ __half As[2][BM][ASTR];
    __shared__ __half Bs[2][BK][BSTR];

    const int e   = blockIdx.z;
    const int m0  = g_offsets[e];
    const int cnt = g_offsets[e + 1] - m0;
    const int mt  = blockIdx.y;
    if (mt * BM >= cnt) return;
    const int n0  = blockIdx.x * BN;

    const __half* Ag = (FFN1 ? g_Hbuf : g_Abuf) + (size_t)(m0 + mt * BM) * KDIM;
    const __half* Bg = (FFN1 ? g_W1h : g_W2h) + (size_t)e * KDIM * NDIM + n0;

    const int tid = threadIdx.x;
    const int wid = tid >> 5, lane = tid & 31;
    const int wm = (wid & 1) * 64;       // 2 warps in M
    const int wn = (wid >> 1) * 32;      // 4 warps in N

    // A: 128x32 halfs = 512 x 16B chunks (2/thread). B: 32x128 = 512 chunks (2/thread).
    auto load_stage = [&](int stg, int k0) {
#pragma unroll
        for (int i = 0; i < 2; i++) {
            int cid = tid * 2 + i;
            int r = cid >> 2, c8 = (cid & 3) * 8;
            cp_async16(smem_u32(&As[stg][r][c8]), Ag + (size_t)r * KDIM + k0 + c8);
        }
#pragma unroll
        for (int i = 0; i < 2; i++) {
            int cid = tid * 2 + i;
            int r = cid >> 4, c8 = (cid & 15) * 8;
            cp_async16(smem_u32(&Bs[stg][r][c8]), Bg + (size_t)(k0 + r) * NDIM + c8);
        }
        asm volatile("cp.async.commit_group;" ::: "memory");
    };

    float acc[4][4][4];
#pragma unroll
    for (int i = 0; i < 4; i++)
#pragma unroll
        for (int j = 0; j < 4; j++)
#pragma unroll
            for (int k = 0; k < 4; k++) acc[i][j][k] = 0.f;

    constexpr int S = KDIM / BK;
    load_stage(0, 0);

    for (int s = 0; s < S; s++) {
        if (s + 1 < S) {
            load_stage((s + 1) & 1, (s + 1) * BK);
            asm volatile("cp.async.wait_group 1;" ::: "memory");
        } else {
            asm volatile("cp.async.wait_group 0;" ::: "memory");
        }
        __syncthreads();
        const int buf = s & 1;
#pragma unroll
        for (int kk = 0; kk < BK; kk += 16) {
            uint32_t a[4][4];
#pragma unroll
            for (int mi = 0; mi < 4; mi++) {
                uint32_t addr = smem_u32(&As[buf][wm + mi * 16 + (lane & 15)][kk + (lane >> 4) * 8]);
                asm volatile("ldmatrix.sync.aligned.m8n8.x4.shared.b16 {%0,%1,%2,%3}, [%4];"
                             : "=r"(a[mi][0]), "=r"(a[mi][1]), "=r"(a[mi][2]), "=r"(a[mi][3])
                             : "r"(addr));
            }
            uint32_t b[4][2];
#pragma unroll
            for (int njp = 0; njp < 4; njp += 2) {
                uint32_t addr = smem_u32(&Bs[buf][kk + (lane & 15)][wn + njp * 8 + (lane >> 4) * 8]);
                uint32_t r0, r1, r2, r3;
                asm volatile("ldmatrix.sync.aligned.m8n8.x4.trans.shared.b16 {%0,%1,%2,%3}, [%4];"
                             : "=r"(r0), "=r"(r1), "=r"(r2), "=r"(r3)
                             : "r"(addr));
                b[njp][0] = r0; b[njp][1] = r1;
                b[njp + 1][0] = r2; b[njp + 1][1] = r3;
            }
#pragma unroll
            for (int mi = 0; mi < 4; mi++)
#pragma unroll
                for (int nj = 0; nj < 4; nj++)
                    asm volatile(
                        "mma.sync.aligned.m16n8k16.row.col.f32.f16.f16.f32 "
                        "{%0,%1,%2,%3},{%4,%5,%6,%7},{%8,%9},{%0,%1,%2,%3};"
                        : "+f"(acc[mi][nj][0]), "+f"(acc[mi][nj][1]),
                          "+f"(acc[mi][nj][2]), "+f"(acc[mi][nj][3])
                        : "r"(a[mi][0]), "r"(a[mi][1]), "r"(a[mi][2]), "r"(a[mi][3]),
                          "r"(b[nj][0]), "r"(b[nj][1]));
        }
        __syncthreads();
    }

    // ---- epilogue ----
#pragma unroll
    for (int mi = 0; mi < 4; mi++) {
#pragma unroll
        for (int nj = 0; nj < 4; nj++) {
            const int r0  = wm + mi * 16 + (lane >> 2);
            const int col = wn + nj * 8 + (lane & 3) * 2;
            const float b0 = bias[(size_t)e * NDIM + n0 + col];
            const float b1 = bias[(size_t)e * NDIM + n0 + col + 1];
#pragma unroll
            for (int h = 0; h < 2; h++) {
                const int r = r0 + h * 8;
                if (mt * BM + r < cnt) {
                    float v0 = acc[mi][nj][2 * h]     + b0;
                    float v1 = acc[mi][nj][2 * h + 1] + b1;
                    const size_t slot = (size_t)(m0 + mt * BM + r);
                    if (FFN1) {
                        v0 = gelu_exact(v0);
                        v1 = gelu_exact(v1);
                        *(__half2*)(g_Abuf + slot * FF_ + n0 + col) =
                            __floats2half2_rn(v0, v1);
                    } else {
                        *(float2*)(g_Ybuf + slot * H_ + n0 + col) = make_float2(v0, v1);
                    }
                }
            }
        }
    }
}

// ---------------- launch (kernel launches ONLY — no other CUDA API calls) ------
extern "C" void kernel_launch(void* const* d_in, const int* in_sizes, int n_in,
                              void* d_out, int out_size) {
    (void)in_sizes; (void)n_in; (void)out_size;
    const float* x    = (const float*)d_in[0];
    const float* rW   = (const float*)d_in[1];
    const float* rb   = (const float*)d_in[2];
    const float* ln_g = (const float*)d_in[3];
    const float* ln_b = (const float*)d_in[4];
    const float* W1   = (const float*)d_in[5];
    const float* b1   = (const float*)d_in[6];
    const float* W2   = (const float*)d_in[7];
    const float* b2   = (const float*)d_in[8];
    float* out = (float*)d_out;

    zero_kernel<<<1, 32>>>();
    convert_kernel<<<2048, 256>>>(W1, W2);
    router_kernel<<<T_, 256>>>(x, rW, rb);
    offsets_kernel<<<1, 32>>>();
    scatter_kernel<<<T_ / 256, 256>>>();
    gather_kernel<<<SLOTS, 256>>>(x, ln_g, ln_b);
    gemm_kernel<H_,  FF_, true ><<<dim3(FF_ / BN, 32, E_), 256>>>(b1);
    gemm_kernel<FF_, H_,  false><<<dim3(H_ / BN, 32, E_), 256>>>(b2);
    combine_kernel<<<T_, 256>>>(x, out);
}

// round 9
// speedup vs baseline: 1.2967x; 1.1193x over previous
#include <cuda_runtime.h>
#include <cuda_fp16.h>
#include <math.h>
#include <stdint.h>

#define B_    2
#define S_    2048
#define H_    1024
#define E_    8
#define FF_   4096
#define T_    (B_ * S_)
#define SLOTS (T_ * 2)
#define SLOTS_PAD (SLOTS + 128)

// ---------------- scratch (static __device__ — no allocations) ----------------
__device__ int    g_counts[E_];
__device__ int    g_offsets[E_ + 1];
__device__ int    g_cursor[E_];
__device__ int    g_tok_e[T_][2];
__device__ float  g_tok_g[T_][2];
__device__ int    g_tok_slot[T_][2];
__device__ float  g_mu[T_];
__device__ float  g_rstd[T_];
__device__ int    g_slot_token[SLOTS_PAD];
__device__ int    g_slot_expert[SLOTS_PAD];
__device__ __half g_Hbuf[(size_t)SLOTS_PAD * H_];          // post-LN rows, fp16
__device__ __half g_Abuf[(size_t)SLOTS_PAD * FF_];         // GELU activations, fp16
__device__ float  g_Ybuf[(size_t)SLOTS_PAD * H_];          // per-slot FFN outputs fp32
__device__ __half g_W1h[(size_t)E_ * H_ * FF_];            // [e][h][f]
__device__ __half g_W2h[(size_t)E_ * FF_ * H_];            // [e][f][h]

// ---------------- small kernels ----------------
// fp32->fp16 weight convert; block 0 also zeroes the expert counters
__global__ void convert_kernel(const float* __restrict__ W1, const float* __restrict__ W2) {
    if (blockIdx.x == 0 && threadIdx.x < E_) g_counts[threadIdx.x] = 0;
    const size_t n4 = (size_t)E_ * H_ * FF_ / 4;
    size_t stride = (size_t)gridDim.x * blockDim.x;
    for (size_t i = (size_t)blockIdx.x * blockDim.x + threadIdx.x; i < n4; i += stride) {
        float4 a = ((const float4*)W1)[i];
        ((__half2*)g_W1h)[2 * i]     = __floats2half2_rn(a.x, a.y);
        ((__half2*)g_W1h)[2 * i + 1] = __floats2half2_rn(a.z, a.w);
        float4 b = ((const float4*)W2)[i];
        ((__half2*)g_W2h)[2 * i]     = __floats2half2_rn(b.x, b.y);
        ((__half2*)g_W2h)[2 * i + 1] = __floats2half2_rn(b.z, b.w);
    }
}

// one block (256 threads) per token: LN stats + router logits + top-2 softmax
__global__ void router_kernel(const float* __restrict__ x,
                              const float* __restrict__ rW,
                              const float* __restrict__ rb) {
    int t = blockIdx.x;
    int tid = threadIdx.x;
    float4 xv = ((const float4*)(x + (size_t)t * H_))[tid];
    float vals[4] = {xv.x, xv.y, xv.z, xv.w};
    float red[10];
#pragma unroll
    for (int i = 0; i < 10; i++) red[i] = 0.f;
#pragma unroll
    for (int j = 0; j < 4; j++) {
        float v = vals[j];
        red[0] += v;
        red[1] += v * v;
        const float4* w4 = (const float4*)(rW + (size_t)(tid * 4 + j) * E_);
        float4 wa = w4[0], wb = w4[1];
        red[2] += v * wa.x; red[3] += v * wa.y; red[4] += v * wa.z; red[5] += v * wa.w;
        red[6] += v * wb.x; red[7] += v * wb.y; red[8] += v * wb.z; red[9] += v * wb.w;
    }
#pragma unroll
    for (int o = 16; o > 0; o >>= 1)
#pragma unroll
        for (int i = 0; i < 10; i++)
            red[i] += __shfl_down_sync(0xffffffffu, red[i], o);
    __shared__ float sred[8][10];
    if ((tid & 31) == 0)
#pragma unroll
        for (int i = 0; i < 10; i++) sred[tid >> 5][i] = red[i];
    __syncthreads();
    if (tid == 0) {
        float f[10];
#pragma unroll
        for (int i = 0; i < 10; i++) {
            float s = 0.f;
#pragma unroll
            for (int w = 0; w < 8; w++) s += sred[w][i];
            f[i] = s;
        }
        float mu  = f[0] * (1.0f / H_);
        float var = f[1] * (1.0f / H_) - mu * mu;
        g_mu[t]   = mu;
        g_rstd[t] = rsqrtf(var + 1e-5f);
        float l[E_];
#pragma unroll
        for (int e = 0; e < E_; e++) l[e] = f[2 + e] + rb[e];
        int i0 = 0;
#pragma unroll
        for (int e = 1; e < E_; e++) if (l[e] > l[i0]) i0 = e;
        int i1 = -1;
#pragma unroll
        for (int e = 0; e < E_; e++)
            if (e != i0 && (i1 < 0 || l[e] > l[i1])) i1 = e;
        float ex = expf(l[i1] - l[i0]);
        float g0 = 1.f / (1.f + ex);
        float g1 = ex / (1.f + ex);
        g_tok_e[t][0] = i0; g_tok_e[t][1] = i1;
        g_tok_g[t][0] = g0; g_tok_g[t][1] = g1;
        atomicAdd(&g_counts[i0], 1);
        atomicAdd(&g_counts[i1], 1);
    }
}

__global__ void offsets_kernel() {
    if (threadIdx.x == 0) {
        int off = 0;
#pragma unroll
        for (int e = 0; e < E_; e++) {
            g_offsets[e] = off;
            g_cursor[e]  = off;
            off += g_counts[e];
        }
        g_offsets[E_] = off;
    }
}

__global__ void scatter_kernel() {
    int t = blockIdx.x * blockDim.x + threadIdx.x;
    if (t < T_) {
#pragma unroll
        for (int s = 0; s < 2; s++) {
            int e = g_tok_e[t][s];
            int pos = atomicAdd(&g_cursor[e], 1);
            g_slot_token[pos]  = t;
            g_slot_expert[pos] = e;
            g_tok_slot[t][s]   = pos;
        }
    }
}

__global__ void gather_kernel(const float* __restrict__ x,
                              const float* __restrict__ ln_g,
                              const float* __restrict__ ln_b) {
    int r = blockIdx.x;
    int t = g_slot_token[r];
    int e = g_slot_expert[r];
    float mu = g_mu[t], rs = g_rstd[t];
    int c = threadIdx.x * 4;
    float4 xv = *(const float4*)(x    + (size_t)t * H_ + c);
    float4 gv = *(const float4*)(ln_g + (size_t)e * H_ + c);
    float4 bv = *(const float4*)(ln_b + (size_t)e * H_ + c);
    float h0 = (xv.x - mu) * rs * gv.x + bv.x;
    float h1 = (xv.y - mu) * rs * gv.y + bv.y;
    float h2 = (xv.z - mu) * rs * gv.z + bv.z;
    float h3 = (xv.w - mu) * rs * gv.w + bv.w;
    __half2* dst = (__half2*)(g_Hbuf + (size_t)r * H_ + c);
    dst[0] = __floats2half2_rn(h0, h1);
    dst[1] = __floats2half2_rn(h2, h3);
}

__global__ void combine_kernel(const float* __restrict__ x, float* __restrict__ out) {
    int t = blockIdx.x;
    int c = threadIdx.x * 4;
    int s0 = g_tok_slot[t][0], s1 = g_tok_slot[t][1];
    float g0 = g_tok_g[t][0],  g1 = g_tok_g[t][1];
    float4 xv = *(const float4*)(x + (size_t)t * H_ + c);
    float4 y0 = *(const float4*)(g_Ybuf + (size_t)s0 * H_ + c);
    float4 y1 = *(const float4*)(g_Ybuf + (size_t)s1 * H_ + c);
    float4 o;
    o.x = xv.x + g0 * y0.x + g1 * y1.x;
    o.y = xv.y + g0 * y0.y + g1 * y1.y;
    o.z = xv.z + g0 * y0.z + g1 * y1.z;
    o.w = xv.w + g0 * y0.w + g1 * y1.w;
    *(float4*)(out + (size_t)t * H_ + c) = o;
}

// ---------------- grouped GEMM (mma.sync fp16, 3-stage, swizzled 48KB smem) ----
// CTA 128x128, BK=32. 8 warps (2M x 4N), warp tile 64x32.
// A stage: [128][32] halfs, 64B rows, 4 chunks, swizzle c^=((r>>1)&3)  -> 8KB
// B stage: [32][128] halfs, 256B rows, 16 chunks, swizzle c^=(r&7)    -> 8KB
// 3 stages * 16KB = 49152 B static shared (exactly the 48KB limit)
#define BM 128
#define BN 128
#define BK 32
#define A_STAGE 8192
#define B_BASE  24576

__device__ __forceinline__ float gelu_exact(float v) {
    return 0.5f * v * (1.0f + erff(v * 0.70710678118654752f));
}
__device__ __forceinline__ void cp_async16(uint32_t dst, const void* src) {
    asm volatile("cp.async.cg.shared.global [%0], [%1], 16;" :: "r"(dst), "l"(src));
}
__device__ __forceinline__ uint32_t smem_u32(const void* p) {
    uint32_t a;
    asm("{ .reg .u64 t; cvta.to.shared.u64 t, %1; cvt.u32.u64 %0, t; }" : "=r"(a) : "l"(p));
    return a;
}

template <int KDIM, int NDIM, bool FFN1>
__global__ void __launch_bounds__(256, 2)
gemm_kernel(const float* __restrict__ bias) {
    __shared__ __align__(1024) char smem_raw[49152];
    const uint32_t sb = smem_u32(smem_raw);

    const int e   = blockIdx.z;
    const int m0  = g_offsets[e];
    const int cnt = g_offsets[e + 1] - m0;
    const int mt  = blockIdx.y;
    if (mt * BM >= cnt) return;
    const int n0  = blockIdx.x * BN;

    const __half* Ag = (FFN1 ? g_Hbuf : g_Abuf) + (size_t)(m0 + mt * BM) * KDIM;
    const __half* Bg = (FFN1 ? g_W1h : g_W2h) + (size_t)e * KDIM * NDIM + n0;

    const int tid = threadIdx.x;
    const int wid = tid >> 5, lane = tid & 31;
    const int wm = (wid & 1) * 64;       // 2 warps in M
    const int wn = (wid >> 1) * 32;      // 4 warps in N

    // A: 512 chunks of 16B (2/thread); B: 512 chunks (2/thread)
    auto load_stage = [&](int stg, int k0) {
        const uint32_t Ab = sb + stg * A_STAGE;
        const uint32_t Bb = sb + B_BASE + stg * A_STAGE;
#pragma unroll
        for (int i = 0; i < 2; i++) {
            int cid = tid * 2 + i;
            int r = cid >> 2, c = cid & 3;
            uint32_t d = Ab + r * 64 + ((c ^ ((r >> 1) & 3)) << 4);
            cp_async16(d, Ag + (size_t)r * KDIM + k0 + c * 8);
        }
#pragma unroll
        for (int i = 0; i < 2; i++) {
            int cid = tid * 2 + i;
            int r = cid >> 4, c = cid & 15;
            uint32_t d = Bb + r * 256 + ((c ^ (r & 7)) << 4);
            cp_async16(d, Bg + (size_t)(k0 + r) * NDIM + c * 8);
        }
        asm volatile("cp.async.commit_group;" ::: "memory");
    };

    float acc[4][4][4];
#pragma unroll
    for (int i = 0; i < 4; i++)
#pragma unroll
        for (int j = 0; j < 4; j++)
#pragma unroll
            for (int k = 0; k < 4; k++) acc[i][j][k] = 0.f;

    constexpr int S = KDIM / BK;
    load_stage(0, 0);
    load_stage(1, BK);

    int stg = 0;
    for (int s = 0; s < S; s++) {
        if (s + 2 < S) {
            load_stage((stg + 2) % 3, (s + 2) * BK);
            asm volatile("cp.async.wait_group 2;" ::: "memory");
        } else if (s + 1 < S) {
            asm volatile("cp.async.wait_group 1;" ::: "memory");
        } else {
            asm volatile("cp.async.wait_group 0;" ::: "memory");
        }
        __syncthreads();
        const uint32_t Ab = sb + stg * A_STAGE;
        const uint32_t Bb = sb + B_BASE + stg * A_STAGE;
#pragma unroll
        for (int kk = 0; kk < BK; kk += 16) {
            uint32_t a[4][4];
#pragma unroll
            for (int mi = 0; mi < 4; mi++) {
                int r = wm + mi * 16 + (lane & 15);
                int c = (kk >> 3) + (lane >> 4);
                uint32_t addr = Ab + r * 64 + ((c ^ ((r >> 1) & 3)) << 4);
                asm volatile("ldmatrix.sync.aligned.m8n8.x4.shared.b16 {%0,%1,%2,%3}, [%4];"
                             : "=r"(a[mi][0]), "=r"(a[mi][1]), "=r"(a[mi][2]), "=r"(a[mi][3])
                             : "r"(addr));
            }
            uint32_t b[4][2];
#pragma unroll
            for (int njp = 0; njp < 4; njp += 2) {
                int r = kk + (lane & 15);
                int c = (wn >> 3) + njp + (lane >> 4);
                uint32_t addr = Bb + r * 256 + ((c ^ (r & 7)) << 4);
                uint32_t r0, r1, r2, r3;
                asm volatile("ldmatrix.sync.aligned.m8n8.x4.trans.shared.b16 {%0,%1,%2,%3}, [%4];"
                             : "=r"(r0), "=r"(r1), "=r"(r2), "=r"(r3)
                             : "r"(addr));
                b[njp][0] = r0; b[njp][1] = r1;
                b[njp + 1][0] = r2; b[njp + 1][1] = r3;
            }
#pragma unroll
            for (int mi = 0; mi < 4; mi++)
#pragma unroll
                for (int nj = 0; nj < 4; nj++)
                    asm volatile(
                        "mma.sync.aligned.m16n8k16.row.col.f32.f16.f16.f32 "
                        "{%0,%1,%2,%3},{%4,%5,%6,%7},{%8,%9},{%0,%1,%2,%3};"
                        : "+f"(acc[mi][nj][0]), "+f"(acc[mi][nj][1]),
                          "+f"(acc[mi][nj][2]), "+f"(acc[mi][nj][3])
                        : "r"(a[mi][0]), "r"(a[mi][1]), "r"(a[mi][2]), "r"(a[mi][3]),
                          "r"(b[nj][0]), "r"(b[nj][1]));
        }
        __syncthreads();
        stg = (stg + 1) % 3;
    }

    // ---- epilogue ----
#pragma unroll
    for (int mi = 0; mi < 4; mi++) {
#pragma unroll
        for (int nj = 0; nj < 4; nj++) {
            const int r0  = wm + mi * 16 + (lane >> 2);
            const int col = wn + nj * 8 + (lane & 3) * 2;
            const float b0 = bias[(size_t)e * NDIM + n0 + col];
            const float b1 = bias[(size_t)e * NDIM + n0 + col + 1];
#pragma unroll
            for (int h = 0; h < 2; h++) {
                const int r = r0 + h * 8;
                if (mt * BM + r < cnt) {
                    float v0 = acc[mi][nj][2 * h]     + b0;
                    float v1 = acc[mi][nj][2 * h + 1] + b1;
                    const size_t slot = (size_t)(m0 + mt * BM + r);
                    if (FFN1) {
                        v0 = gelu_exact(v0);
                        v1 = gelu_exact(v1);
                        *(__half2*)(g_Abuf + slot * FF_ + n0 + col) =
                            __floats2half2_rn(v0, v1);
                    } else {
                        *(float2*)(g_Ybuf + slot * H_ + n0 + col) = make_float2(v0, v1);
                    }
                }
            }
        }
    }
}

// ---------------- launch (kernel launches ONLY — no other CUDA API calls) ------
extern "C" void kernel_launch(void* const* d_in, const int* in_sizes, int n_in,
                              void* d_out, int out_size) {
    (void)in_sizes; (void)n_in; (void)out_size;
    const float* x    = (const float*)d_in[0];
    const float* rW   = (const float*)d_in[1];
    const float* rb   = (const float*)d_in[2];
    const float* ln_g = (const float*)d_in[3];
    const float* ln_b = (const float*)d_in[4];
    const float* W1   = (const float*)d_in[5];
    const float* b1   = (const float*)d_in[6];
    const float* W2   = (const float*)d_in[7];
    const float* b2   = (const float*)d_in[8];
    float* out = (float*)d_out;

    convert_kernel<<<2048, 256>>>(W1, W2);
    router_kernel<<<T_, 256>>>(x, rW, rb);
    offsets_kernel<<<1, 32>>>();
    scatter_kernel<<<T_ / 256, 256>>>();
    gather_kernel<<<SLOTS, 256>>>(x, ln_g, ln_b);
    gemm_kernel<H_,  FF_, true ><<<dim3(FF_ / BN, 32, E_), 256>>>(b1);
    gemm_kernel<FF_, H_,  false><<<dim3(H_ / BN, 32, E_), 256>>>(b2);
    combine_kernel<<<T_, 256>>>(x, out);
}